// round 10
// baseline (speedup 1.0000x reference)
#include <cuda_runtime.h>
#include <cstdint>

#define KIDS 64
#define NCANDS 16
#define NTHR 512
#define IDSW 4                   // ids per warp (16 warps x 4 = 64)
#define BCH 8                    // chunks per batch: 8 x 128 px = 1024 px
#define SENTI 0x7FFFFFFF

__device__ __forceinline__ uint32_t rotl32(uint32_t v, int d) {
    return __funnelshift_l(v, v, d);
}

// JAX threefry2x32 (20 rounds), bit-exact.
__device__ __forceinline__ void tf2x32(uint32_t k0, uint32_t k1,
                                       uint32_t x0, uint32_t x1,
                                       uint32_t& o0, uint32_t& o1) {
    uint32_t k2 = k0 ^ k1 ^ 0x1BD11BDAu;
    x0 += k0; x1 += k1;
#define R_(r) { x0 += x1; x1 = rotl32(x1, (r)); x1 ^= x0; }
    R_(13) R_(15) R_(26) R_(6)   x0 += k1; x1 += k2 + 1u;
    R_(17) R_(29) R_(16) R_(24)  x0 += k2; x1 += k0 + 2u;
    R_(13) R_(15) R_(26) R_(6)   x0 += k0; x1 += k1 + 3u;
    R_(17) R_(29) R_(16) R_(24)  x0 += k1; x1 += k2 + 4u;
    R_(13) R_(15) R_(26) R_(6)   x0 += k2; x1 += k0 + 5u;
#undef R_
    o0 = x0; o1 = x1;
}

// Warp-uniform: fold the two smallest positions of id k in this 128-px chunk
// into (f, s, done). x = this lane's 4 consecutive ids. No atomics.
__device__ __forceinline__ void scan_chunk(int4 x, int k, int base,
                                           int& f, int& s, bool& done) {
    unsigned m = (x.x == k ? 1u : 0u) | (x.y == k ? 2u : 0u) |
                 (x.z == k ? 4u : 0u) | (x.w == k ? 8u : 0u);
    unsigned b = __ballot_sync(0xffffffffu, m != 0u);
    if (!b) return;
    int l1 = __ffs(b) - 1;
    unsigned m1 = __shfl_sync(0xffffffffu, m, l1);
    int pos1 = base + l1 * 4 + (__ffs(m1) - 1);
    int pos2 = -1;
    unsigned m1r = m1 & (m1 - 1);
    if (m1r) {
        pos2 = base + l1 * 4 + (__ffs(m1r) - 1);
    } else {
        unsigned b2 = b & (b - 1);
        if (b2) {
            int l2 = __ffs(b2) - 1;
            unsigned m2 = __shfl_sync(0xffffffffu, m, l2);
            pos2 = base + l2 * 4 + (__ffs(m2) - 1);
        }
    }
    if (f == SENTI) {
        f = pos1;
        if (pos2 >= 0) { s = pos2; done = true; }
    } else {
        s = pos1; done = true;
    }
}

__device__ __forceinline__ void load_batch(int4* v, const int* __restrict__ mask,
                                           int base, int HW, int lane) {
    #pragma unroll
    for (int c = 0; c < BCH; c++) {
        int p = base + c * 128 + lane * 4;
        if (p + 3 < HW) {
            v[c] = *reinterpret_cast<const int4*>(mask + p);
        } else {
            v[c] = make_int4(-1, -1, -1, -1);
            if (p     < HW) v[c].x = mask[p];
            if (p + 1 < HW) v[c].y = mask[p + 1];
            if (p + 2 < HW) v[c].z = mask[p + 2];
        }
    }
}

__global__ void __launch_bounds__(NTHR)
single_kernel(const float* __restrict__ sem, const int* __restrict__ mask,
              float* __restrict__ out, int HW, int BC) {
    __shared__ float sPer[KIDS];
    __shared__ int   sVal[KIDS];

    int t = threadIdx.x, warp = t >> 5, lane = t & 31;
    int kbase = warp * IDSW;           // this warp owns ids kbase..kbase+3

    // ---- negatives: 2 candidates per lane (4 ids x 16 cands = 64/warp) ----
    uint32_t kk0, kk1;
    tf2x32(0u, 1u, 0u, 1u, kk0, kk1);            // child key of split(key(1))
    int km[2], cand[2], cval[2];
    #pragma unroll
    for (int i = 0; i < 2; i++) {
        km[i] = kbase + i * 2 + (lane >> 4);     // lanes 0-15: even id, 16-31: odd
        uint32_t o0, o1;
        tf2x32(kk0, kk1, 0u, (uint32_t)(km[i] * NCANDS + (lane & 15)), o0, o1);
        cand[i] = (int)((o0 ^ o1) % (uint32_t)HW);
        cval[i] = __ldg(mask + cand[i]);         // gathers issued...
    }

    // ---- scan batch 0: loads issued before cval is consumed (same round) ----
    int4 v[BCH];
    load_batch(v, mask, 0, HW, lane);

    // resolve negatives (first candidate whose id differs; else candidate 0)
    int neg[IDSW];
    #pragma unroll
    for (int i = 0; i < 2; i++) {
        unsigned bal = __ballot_sync(0xffffffffu, cval[i] != km[i]);
        unsigned lo = bal & 0xFFFFu, hi = bal >> 16;
        neg[i * 2]     = __shfl_sync(0xffffffffu, cand[i], lo ? (__ffs(lo) - 1) : 0);
        neg[i * 2 + 1] = __shfl_sync(0xffffffffu, cand[i], hi ? (16 + __ffs(hi) - 1) : 16);
    }

    // ---- per-warp ballot scan, batches of 1024 px until all 4 ids done ----
    int f[IDSW], s[IDSW];
    bool d[IDSW];
    #pragma unroll
    for (int j = 0; j < IDSW; j++) { f[j] = SENTI; s[j] = SENTI; d[j] = false; }
    d[0] = (kbase == 0);               // background id skipped (never valid)

    int base = 0;
    while (true) {
        #pragma unroll
        for (int ch = 0; ch < BCH; ch++) {
            #pragma unroll
            for (int j = 0; j < IDSW; j++)
                if (!d[j]) scan_chunk(v[ch], kbase + j, base + ch * 128,
                                      f[j], s[j], d[j]);
        }
        base += BCH * 128;
        if ((d[0] && d[1] && d[2] && d[3]) || base >= HW) break;  // exact fallback
        load_batch(v, mask, base, HW, lane);
    }

    // ---- finalize 4 ids: one batched gather round, warp-local ----
    float dap[IDSW], dan[IDSW];
    int fi[IDSW], si[IDSW];
    bool val[IDSW];
    #pragma unroll
    for (int j = 0; j < IDSW; j++) {
        val[j] = (s[j] != SENTI) && (kbase + j != 0);
        fi[j] = min(f[j], HW - 1);
        si[j] = min(s[j], HW - 1);
        dap[j] = 0.f; dan[j] = 0.f;
    }
    #pragma unroll
    for (int i = 0; i < 4; i++) {                // covers BC <= 128 (BC = 76)
        int c = lane + i * 32;
        if (c < BC) {
            size_t off = (size_t)c * (size_t)HW;
            #pragma unroll
            for (int j = 0; j < IDSW; j++) {
                float a = __ldg(sem + off + fi[j]);
                float p = __ldg(sem + off + si[j]);
                float n = __ldg(sem + off + neg[j]);
                float e;
                e = a - p + 1e-6f; dap[j] = fmaf(e, e, dap[j]);
                e = a - n + 1e-6f; dan[j] = fmaf(e, e, dan[j]);
            }
        }
    }
    for (int c = lane + 128; c < BC; c += 32) {  // generic tail (unused here)
        size_t off = (size_t)c * (size_t)HW;
        #pragma unroll
        for (int j = 0; j < IDSW; j++) {
            float a = __ldg(sem + off + fi[j]);
            float p = __ldg(sem + off + si[j]);
            float n = __ldg(sem + off + neg[j]);
            float e;
            e = a - p + 1e-6f; dap[j] = fmaf(e, e, dap[j]);
            e = a - n + 1e-6f; dan[j] = fmaf(e, e, dan[j]);
        }
    }
    #pragma unroll
    for (int o = 16; o; o >>= 1) {
        #pragma unroll
        for (int j = 0; j < IDSW; j++) {
            dap[j] += __shfl_down_sync(0xffffffffu, dap[j], o);
            dan[j] += __shfl_down_sync(0xffffffffu, dan[j], o);
        }
    }
    if (lane == 0) {
        #pragma unroll
        for (int j = 0; j < IDSW; j++) {
            float per = fmaxf(sqrtf(dap[j]) - sqrtf(dan[j]) + 1.0f, 0.0f);
            sPer[kbase + j] = val[j] ? per : 0.0f;
            sVal[kbase + j] = val[j] ? 1 : 0;
        }
    }
    __syncthreads();                   // the only block barrier

    // ---- warp 0: fixed-order shfl reduction over 64 ids (deterministic) ----
    if (warp == 0) {
        float tot = sPer[lane] + sPer[lane + 32];
        int   c   = sVal[lane] + sVal[lane + 32];
        #pragma unroll
        for (int o = 16; o; o >>= 1) {
            tot += __shfl_down_sync(0xffffffffu, tot, o);
            c   += __shfl_down_sync(0xffffffffu, c, o);
        }
        if (lane == 0) out[0] = (c > 0) ? tot / (float)c : 0.0f;
    }
}

extern "C" void kernel_launch(void* const* d_in, const int* in_sizes, int n_in,
                              void* d_out, int out_size) {
    const float* sem  = (const float*)d_in[0];
    const int*   mask = (const int*)d_in[1];
    float*       out  = (float*)d_out;
    int HW = in_sizes[1];
    int BC = in_sizes[0] / HW;

    single_kernel<<<1, NTHR>>>(sem, mask, out, HW, BC);
}

// round 11
// speedup vs baseline: 1.2586x; 1.2586x over previous
#include <cuda_runtime.h>
#include <cstdint>

#define KIDS 64
#define NCANDS 16
#define NTHR 1024
#define BCH 8                    // chunks per batch: 8 x 128 px = 1024 px
#define SENTI 0x7FFFFFFF

__device__ __forceinline__ uint32_t rotl32(uint32_t v, int d) {
    return __funnelshift_l(v, v, d);
}

// JAX threefry2x32 (20 rounds), bit-exact.
__device__ __forceinline__ void tf2x32(uint32_t k0, uint32_t k1,
                                       uint32_t x0, uint32_t x1,
                                       uint32_t& o0, uint32_t& o1) {
    uint32_t k2 = k0 ^ k1 ^ 0x1BD11BDAu;
    x0 += k0; x1 += k1;
#define R_(r) { x0 += x1; x1 = rotl32(x1, (r)); x1 ^= x0; }
    R_(13) R_(15) R_(26) R_(6)   x0 += k1; x1 += k2 + 1u;
    R_(17) R_(29) R_(16) R_(24)  x0 += k2; x1 += k0 + 2u;
    R_(13) R_(15) R_(26) R_(6)   x0 += k0; x1 += k1 + 3u;
    R_(17) R_(29) R_(16) R_(24)  x0 += k1; x1 += k2 + 4u;
    R_(13) R_(15) R_(26) R_(6)   x0 += k2; x1 += k0 + 5u;
#undef R_
    o0 = x0; o1 = x1;
}

// Warp-uniform: fold the two smallest positions of id k in this 128-px chunk
// into (f, s, done). x = this lane's 4 consecutive ids. No atomics.
__device__ __forceinline__ void scan_chunk(int4 x, int k, int base,
                                           int& f, int& s, bool& done) {
    unsigned m = (x.x == k ? 1u : 0u) | (x.y == k ? 2u : 0u) |
                 (x.z == k ? 4u : 0u) | (x.w == k ? 8u : 0u);
    unsigned b = __ballot_sync(0xffffffffu, m != 0u);
    if (!b) return;
    int l1 = __ffs(b) - 1;
    unsigned m1 = __shfl_sync(0xffffffffu, m, l1);
    int pos1 = base + l1 * 4 + (__ffs(m1) - 1);
    int pos2 = -1;
    unsigned m1r = m1 & (m1 - 1);
    if (m1r) {
        pos2 = base + l1 * 4 + (__ffs(m1r) - 1);
    } else {
        unsigned b2 = b & (b - 1);
        if (b2) {
            int l2 = __ffs(b2) - 1;
            unsigned m2 = __shfl_sync(0xffffffffu, m, l2);
            pos2 = base + l2 * 4 + (__ffs(m2) - 1);
        }
    }
    if (f == SENTI) {
        f = pos1;
        if (pos2 >= 0) { s = pos2; done = true; }
    } else {
        s = pos1; done = true;
    }
}

__device__ __forceinline__ void load_batch(int4* v, const int* __restrict__ mask,
                                           int base, int HW, int lane) {
    #pragma unroll
    for (int c = 0; c < BCH; c++) {
        int p = base + c * 128 + lane * 4;
        if (p + 3 < HW) {
            v[c] = *reinterpret_cast<const int4*>(mask + p);
        } else {
            v[c] = make_int4(-1, -1, -1, -1);
            if (p     < HW) v[c].x = mask[p];
            if (p + 1 < HW) v[c].y = mask[p + 1];
            if (p + 2 < HW) v[c].z = mask[p + 2];
        }
    }
}

__global__ void __launch_bounds__(NTHR)
single_kernel(const float* __restrict__ sem, const int* __restrict__ mask,
              float* __restrict__ out, int HW, int BC) {
    __shared__ float sPer[KIDS];
    __shared__ int   sVal[KIDS];

    int t = threadIdx.x, warp = t >> 5, lane = t & 31;
    int k0 = warp * 2, k1 = k0 + 1;    // this warp owns ids k0, k1 end-to-end

    // ---- negatives: lanes 0-15 carry k0's candidates, 16-31 carry k1's ----
    uint32_t kk0, kk1;
    tf2x32(0u, 1u, 0u, 1u, kk0, kk1);            // child key of split(key(1))
    int kmine = (lane < 16) ? k0 : k1;
    uint32_t o0, o1;
    tf2x32(kk0, kk1, 0u, (uint32_t)(kmine * NCANDS + (lane & 15)), o0, o1);
    int cand = (int)((o0 ^ o1) % (uint32_t)HW);
    int candval = __ldg(mask + cand);            // gather issued...

    // ---- scan batch 0: loads issued before candval is consumed (same round) --
    int4 v[BCH];
    load_batch(v, mask, 0, HW, lane);

    // resolve negatives (first candidate whose id differs; else candidate 0)
    unsigned bal = __ballot_sync(0xffffffffu, candval != kmine);
    unsigned b0m = bal & 0xFFFFu, b1m = bal >> 16;
    int neg0 = __shfl_sync(0xffffffffu, cand, b0m ? (__ffs(b0m) - 1) : 0);
    int neg1 = __shfl_sync(0xffffffffu, cand, b1m ? (16 + __ffs(b1m) - 1) : 16);

    // ---- per-warp ballot scan, batches of 1024 px until both ids done ----
    int f0 = SENTI, s0 = SENTI, f1 = SENTI, s1 = SENTI;
    bool d0 = (k0 == 0);               // background id skipped (never valid)
    bool d1 = false;
    int base = 0;
    while (true) {
        #pragma unroll
        for (int ch = 0; ch < BCH; ch++) {
            if (!d0) scan_chunk(v[ch], k0, base + ch * 128, f0, s0, d0);
            if (!d1) scan_chunk(v[ch], k1, base + ch * 128, f1, s1, d1);
        }
        base += BCH * 128;
        if ((d0 && d1) || base >= HW) break;     // exact fallback: keep going
        load_batch(v, mask, base, HW, lane);
    }

    // ---- finalize both ids: one batched gather round, warp-local ----
    bool val0 = (s0 != SENTI) && (k0 != 0);
    bool val1 = (s1 != SENTI);
    int fi0 = min(f0, HW - 1), si0 = min(s0, HW - 1);
    int fi1 = min(f1, HW - 1), si1 = min(s1, HW - 1);

    float dap0 = 0.f, dan0 = 0.f, dap1 = 0.f, dan1 = 0.f;
    #pragma unroll
    for (int i = 0; i < 4; i++) {                // covers BC <= 128 (BC = 76)
        int c = lane + i * 32;
        if (c < BC) {
            size_t off = (size_t)c * (size_t)HW;
            float a0 = __ldg(sem + off + fi0);
            float p0 = __ldg(sem + off + si0);
            float n0 = __ldg(sem + off + neg0);
            float a1 = __ldg(sem + off + fi1);
            float p1 = __ldg(sem + off + si1);
            float n1 = __ldg(sem + off + neg1);
            float e;
            e = a0 - p0 + 1e-6f; dap0 = fmaf(e, e, dap0);
            e = a0 - n0 + 1e-6f; dan0 = fmaf(e, e, dan0);
            e = a1 - p1 + 1e-6f; dap1 = fmaf(e, e, dap1);
            e = a1 - n1 + 1e-6f; dan1 = fmaf(e, e, dan1);
        }
    }
    for (int c = lane + 128; c < BC; c += 32) {  // generic tail (unused here)
        size_t off = (size_t)c * (size_t)HW;
        float a0 = __ldg(sem + off + fi0), p0 = __ldg(sem + off + si0),
              n0 = __ldg(sem + off + neg0);
        float a1 = __ldg(sem + off + fi1), p1 = __ldg(sem + off + si1),
              n1 = __ldg(sem + off + neg1);
        float e;
        e = a0 - p0 + 1e-6f; dap0 = fmaf(e, e, dap0);
        e = a0 - n0 + 1e-6f; dan0 = fmaf(e, e, dan0);
        e = a1 - p1 + 1e-6f; dap1 = fmaf(e, e, dap1);
        e = a1 - n1 + 1e-6f; dan1 = fmaf(e, e, dan1);
    }
    #pragma unroll
    for (int o = 16; o; o >>= 1) {
        dap0 += __shfl_down_sync(0xffffffffu, dap0, o);
        dan0 += __shfl_down_sync(0xffffffffu, dan0, o);
        dap1 += __shfl_down_sync(0xffffffffu, dap1, o);
        dan1 += __shfl_down_sync(0xffffffffu, dan1, o);
    }
    if (lane == 0) {
        float per0 = fmaxf(sqrtf(dap0) - sqrtf(dan0) + 1.0f, 0.0f);
        float per1 = fmaxf(sqrtf(dap1) - sqrtf(dan1) + 1.0f, 0.0f);
        sPer[k0] = val0 ? per0 : 0.0f;  sVal[k0] = val0 ? 1 : 0;
        sPer[k1] = val1 ? per1 : 0.0f;  sVal[k1] = val1 ? 1 : 0;
    }
    __syncthreads();                   // the only block barrier

    // ---- warp 0: fixed-order shfl reduction over 64 ids (deterministic) ----
    if (warp == 0) {
        float tot = sPer[lane] + sPer[lane + 32];
        int   c   = sVal[lane] + sVal[lane + 32];
        #pragma unroll
        for (int o = 16; o; o >>= 1) {
            tot += __shfl_down_sync(0xffffffffu, tot, o);
            c   += __shfl_down_sync(0xffffffffu, c, o);
        }
        if (lane == 0) out[0] = (c > 0) ? tot / (float)c : 0.0f;
    }
}

extern "C" void kernel_launch(void* const* d_in, const int* in_sizes, int n_in,
                              void* d_out, int out_size) {
    const float* sem  = (const float*)d_in[0];
    const int*   mask = (const int*)d_in[1];
    float*       out  = (float*)d_out;
    int HW = in_sizes[1];
    int BC = in_sizes[0] / HW;

    single_kernel<<<1, NTHR>>>(sem, mask, out, HW, BC);
}

// round 12
// speedup vs baseline: 2.1236x; 1.6873x over previous
#include <cuda_runtime.h>
#include <cstdint>

#define KIDS 64
#define NCANDS 16
#define BTHR 256                 // threads per block; 1 block per id
#define SENTI 0x7FFFFFFF
#define SENTPAIR 0x7FFFFFFF7FFFFFFFULL

// Per-id results: every block writes its own slot every launch before the
// done-counter arrive, so no initialization pass is needed.
__device__ float g_per[KIDS];
__device__ int   g_val[KIDS];
__device__ unsigned g_done = 0;  // reset by the last block each launch

__device__ __forceinline__ uint32_t rotl32(uint32_t v, int d) {
    return __funnelshift_l(v, v, d);
}

// JAX threefry2x32 (20 rounds), bit-exact.
__device__ __forceinline__ void tf2x32(uint32_t k0, uint32_t k1,
                                       uint32_t x0, uint32_t x1,
                                       uint32_t& o0, uint32_t& o1) {
    uint32_t k2 = k0 ^ k1 ^ 0x1BD11BDAu;
    x0 += k0; x1 += k1;
#define R_(r) { x0 += x1; x1 = rotl32(x1, (r)); x1 ^= x0; }
    R_(13) R_(15) R_(26) R_(6)   x0 += k1; x1 += k2 + 1u;
    R_(17) R_(29) R_(16) R_(24)  x0 += k2; x1 += k0 + 2u;
    R_(13) R_(15) R_(26) R_(6)   x0 += k0; x1 += k1 + 3u;
    R_(17) R_(29) R_(16) R_(24)  x0 += k1; x1 += k2 + 4u;
    R_(13) R_(15) R_(26) R_(6)   x0 += k2; x1 += k0 + 5u;
#undef R_
    o0 = x0; o1 = x1;
}

// Two-smallest merge: (f1,s1) += (f2,s2)
__device__ __forceinline__ void merge2(int& f1, int& s1, int f2, int s2) {
    int nf = min(f1, f2);
    int ns = min(max(f1, f2), min(s1, s2));
    f1 = nf; s1 = ns;
}

__global__ void __launch_bounds__(BTHR)
per_id_kernel(const float* __restrict__ sem, const int* __restrict__ mask,
              float* __restrict__ out, int HW, int BC) {
    __shared__ unsigned long long sPair[BTHR / 32];
    __shared__ float2 sSq[BTHR];
    __shared__ int sNeg, sLast;

    int t = threadIdx.x, warp = t >> 5, lane = t & 31;
    int k = blockIdx.x;              // this block owns id k

    // ---- candidates for id k (warp 0, lanes 0-15); gather issued early ----
    int cand = 0, candval = 0;
    if (warp == 0) {
        uint32_t kk0, kk1;
        tf2x32(0u, 1u, 0u, 1u, kk0, kk1);        // child key of split(key(1))
        if (lane < NCANDS) {
            uint32_t o0, o1;
            tf2x32(kk0, kk1, 0u, (uint32_t)(k * NCANDS + lane), o0, o1);
            cand = (int)((o0 ^ o1) % (uint32_t)HW);
            candval = __ldg(mask + cand);        // in flight...
        }
    }

    // ---- batch 0 of the scan: issued before candval is consumed ----
    int base = 0;
    int p = t * 4;
    int4 v = make_int4(-1, -1, -1, -1);
    if (p + 3 < HW) v = *reinterpret_cast<const int4*>(mask + p);
    else {
        if (p     < HW) v.x = mask[p];
        if (p + 1 < HW) v.y = mask[p + 1];
        if (p + 2 < HW) v.z = mask[p + 2];
    }

    // resolve negative (first candidate whose id differs; else candidate 0)
    if (warp == 0) {
        bool ok = (lane < NCANDS) && (candval != k);
        unsigned bal = __ballot_sync(0xffffffffu, ok) & 0xFFFFu;
        int neg = __shfl_sync(0xffffffffu, cand, bal ? (__ffs(bal) - 1) : 0);
        if (lane == 0) sNeg = neg;
    }

    // ---- block scan: two smallest positions of id k (batches of 1024 px) ----
    int bf = SENTI, bs = SENTI;      // block-uniform running two-min
    while (true) {
        // local two-min from this thread's 4 pixels
        unsigned m = (v.x == k ? 1u : 0u) | (v.y == k ? 2u : 0u) |
                     (v.z == k ? 4u : 0u) | (v.w == k ? 8u : 0u);
        int fl = SENTI, sl = SENTI;
        if (m) {
            fl = base + t * 4 + (__ffs(m) - 1);
            unsigned mr = m & (m - 1);
            if (mr) sl = base + t * 4 + (__ffs(mr) - 1);
        }
        // warp two-min
        #pragma unroll
        for (int o = 16; o; o >>= 1) {
            int f2 = __shfl_down_sync(0xffffffffu, fl, o);
            int s2 = __shfl_down_sync(0xffffffffu, sl, o);
            merge2(fl, sl, f2, s2);
        }
        if (lane == 0)
            sPair[warp] = ((unsigned long long)(unsigned)fl << 32) | (unsigned)sl;
        __syncthreads();
        // warp 0 merges the 8 per-warp pairs
        if (warp == 0) {
            unsigned long long pp = (lane < BTHR / 32) ? sPair[lane] : SENTPAIR;
            int fl2 = (int)(unsigned)(pp >> 32), sl2 = (int)(unsigned)pp;
            #pragma unroll
            for (int o = 4; o; o >>= 1) {
                int f2 = __shfl_down_sync(0xffffffffu, fl2, o);
                int s2 = __shfl_down_sync(0xffffffffu, sl2, o);
                merge2(fl2, sl2, f2, s2);
            }
            if (lane == 0)
                sPair[0] = ((unsigned long long)(unsigned)fl2 << 32) | (unsigned)sl2;
        }
        __syncthreads();
        {
            unsigned long long pp = sPair[0];
            merge2(bf, bs, (int)(unsigned)(pp >> 32), (int)(unsigned)pp);
        }
        base += BTHR * 4;
        if (bs != SENTI || base >= HW) break;    // exact fallback: keep going
        __syncthreads();                          // WAR guard on sPair
        p = base + t * 4;
        v = make_int4(-1, -1, -1, -1);
        if (p + 3 < HW) v = *reinterpret_cast<const int4*>(mask + p);
        else {
            if (p     < HW) v.x = mask[p];
            if (p + 1 < HW) v.y = mask[p + 1];
            if (p + 2 < HW) v.z = mask[p + 2];
        }
    }

    bool valid = (bs != SENTI) && (k != 0);
    int fi = min(bf, HW - 1);
    int si = min(bs, HW - 1);
    int neg = sNeg;                  // scan barriers ordered this write

    // ---- finalize: channel-parallel gathers (1 channel per thread) ----
    float dap = 0.f, dan = 0.f;
    for (int c = t; c < BC; c += BTHR) {
        size_t off = (size_t)c * (size_t)HW;
        float a = __ldg(sem + off + fi);
        float pv = __ldg(sem + off + si);
        float n = __ldg(sem + off + neg);
        float e1 = a - pv + 1e-6f;
        float e2 = a - n  + 1e-6f;
        dap = fmaf(e1, e1, dap);
        dan = fmaf(e2, e2, dan);
    }
    sSq[t] = make_float2(dap, dan);
    __syncthreads();
    // warp 0: deterministic fixed-order reduction over 256 partials
    if (warp == 0) {
        float ta = 0.f, tn = 0.f;
        #pragma unroll
        for (int i = 0; i < BTHR / 32; i++) {
            float2 q = sSq[lane + i * 32];
            ta += q.x; tn += q.y;
        }
        #pragma unroll
        for (int o = 16; o; o >>= 1) {
            ta += __shfl_down_sync(0xffffffffu, ta, o);
            tn += __shfl_down_sync(0xffffffffu, tn, o);
        }
        if (lane == 0) {
            float per = fmaxf(sqrtf(ta) - sqrtf(tn) + 1.0f, 0.0f);
            g_per[k] = valid ? per : 0.0f;
            g_val[k] = valid ? 1 : 0;
        }
    }
    __threadfence();
    __syncthreads();
    if (t == 0) {
        unsigned prev = atomicAdd(&g_done, 1u);
        sLast = (prev == gridDim.x - 1) ? 1 : 0;
    }
    __syncthreads();
    if (!sLast) return;

    // ---- last block: reduce the 64 per-id results, write the scalar ----
    __threadfence();
    if (warp == 0) {
        float tot = __ldcg(&g_per[lane]) + __ldcg(&g_per[lane + 32]);
        int   c   = __ldcg(&g_val[lane]) + __ldcg(&g_val[lane + 32]);
        #pragma unroll
        for (int o = 16; o; o >>= 1) {
            tot += __shfl_down_sync(0xffffffffu, tot, o);
            c   += __shfl_down_sync(0xffffffffu, c, o);
        }
        if (lane == 0) {
            out[0] = (c > 0) ? tot / (float)c : 0.0f;
            g_done = 0;              // reset for next graph replay
        }
    }
}

extern "C" void kernel_launch(void* const* d_in, const int* in_sizes, int n_in,
                              void* d_out, int out_size) {
    const float* sem  = (const float*)d_in[0];
    const int*   mask = (const int*)d_in[1];
    float*       out  = (float*)d_out;
    int HW = in_sizes[1];
    int BC = in_sizes[0] / HW;

    per_id_kernel<<<KIDS, BTHR>>>(sem, mask, out, HW, BC);
}

// round 13
// speedup vs baseline: 2.1630x; 1.0185x over previous
#include <cuda_runtime.h>
#include <cstdint>

#define KIDS 64
#define NCANDS 16
#define BTHR 256                 // threads per block; 1 block per id
#define SENTI 0x7FFFFFFF

// Single packed accumulator: bits[0:7)=arrive count, [7:13)=valid count,
// [13:64)=sum of per-instance losses in 2^30 fixed point (exact int adds =>
// deterministic across replays regardless of arrival order).
__device__ unsigned long long g_acc = 0ULL;   // reset by the winner each launch

// ---------------- compile-time threefry (host constexpr mirror) ----------------
constexpr uint32_t crotl(uint32_t v, int d) { return (v << d) | (v >> (32 - d)); }
constexpr unsigned long long ctf(uint32_t k0, uint32_t k1,
                                 uint32_t x0, uint32_t x1) {
    uint32_t k2 = k0 ^ k1 ^ 0x1BD11BDAu;
    x0 += k0; x1 += k1;
#define CR_(r) { x0 += x1; x1 = crotl(x1, (r)); x1 ^= x0; }
    CR_(13) CR_(15) CR_(26) CR_(6)   x0 += k1; x1 += k2 + 1u;
    CR_(17) CR_(29) CR_(16) CR_(24)  x0 += k2; x1 += k0 + 2u;
    CR_(13) CR_(15) CR_(26) CR_(6)   x0 += k0; x1 += k1 + 3u;
    CR_(17) CR_(29) CR_(16) CR_(24)  x0 += k1; x1 += k2 + 4u;
    CR_(13) CR_(15) CR_(26) CR_(6)   x0 += k2; x1 += k0 + 5u;
#undef CR_
    return ((unsigned long long)x0 << 32) | x1;
}
// child key of split(key(1)) — fully input-independent
constexpr unsigned long long KKC = ctf(0u, 1u, 0u, 1u);
#define KK0 ((uint32_t)(KKC >> 32))
#define KK1 ((uint32_t)KKC)

// ---------------- runtime threefry (device, bit-exact) ----------------
__device__ __forceinline__ uint32_t rotl32(uint32_t v, int d) {
    return __funnelshift_l(v, v, d);
}
__device__ __forceinline__ void tf2x32(uint32_t k0, uint32_t k1,
                                       uint32_t x0, uint32_t x1,
                                       uint32_t& o0, uint32_t& o1) {
    uint32_t k2 = k0 ^ k1 ^ 0x1BD11BDAu;
    x0 += k0; x1 += k1;
#define R_(r) { x0 += x1; x1 = rotl32(x1, (r)); x1 ^= x0; }
    R_(13) R_(15) R_(26) R_(6)   x0 += k1; x1 += k2 + 1u;
    R_(17) R_(29) R_(16) R_(24)  x0 += k2; x1 += k0 + 2u;
    R_(13) R_(15) R_(26) R_(6)   x0 += k0; x1 += k1 + 3u;
    R_(17) R_(29) R_(16) R_(24)  x0 += k1; x1 += k2 + 4u;
    R_(13) R_(15) R_(26) R_(6)   x0 += k2; x1 += k0 + 5u;
#undef R_
    o0 = x0; o1 = x1;
}

__global__ void __launch_bounds__(BTHR)
per_id_kernel(const float* __restrict__ sem, const int* __restrict__ mask,
              float* __restrict__ out, int HW, int BC) {
    __shared__ int sF, sS, sNeg;
    __shared__ float2 sSq[BTHR];

    int t = threadIdx.x, warp = t >> 5, lane = t & 31;
    int k = blockIdx.x;              // this block owns id k

    if (t == 0) { sF = SENTI; sS = SENTI; }

    // ---- batch 0 of the scan: issued first, no dependencies ----
    int base = 0;
    int p = t * 4;
    int4 v = make_int4(-1, -1, -1, -1);
    if (p + 3 < HW) v = *reinterpret_cast<const int4*>(mask + p);
    else {
        if (p     < HW) v.x = mask[p];
        if (p + 1 < HW) v.y = mask[p + 1];
        if (p + 2 < HW) v.z = mask[p + 2];
    }

    // ---- candidates (warp 0): one runtime threefry, overlapped with loads ----
    int cand = 0, candval = 0;
    if (warp == 0 && lane < NCANDS) {
        uint32_t o0, o1;
        tf2x32(KK0, KK1, 0u, (uint32_t)(k * NCANDS + lane), o0, o1);
        cand = (int)((o0 ^ o1) % (uint32_t)HW);
        candval = __ldg(mask + cand);            // in flight...
    }

    // ---- block scan: two smallest positions of id k ----
    while (true) {
        // per-thread two-min over its 4 pixels
        unsigned m = (v.x == k ? 1u : 0u) | (v.y == k ? 2u : 0u) |
                     (v.z == k ? 4u : 0u) | (v.w == k ? 8u : 0u);
        int fl = SENTI, sl = SENTI;
        if (m) {
            fl = base + t * 4 + (__ffs(m) - 1);
            unsigned mr = m & (m - 1);
            if (mr) sl = base + t * 4 + (__ffs(mr) - 1);
        }
        __syncthreads();     // orders sF/sS init (and prior batch reads) before atomics
        // displaced-value two-min merge into smem (linearizable, ~16 contenders)
        if (fl != SENTI) {
            int cnd;
            if (fl < sF) {
                int prev = atomicMin(&sF, fl);
                cnd = (prev == SENTI) ? SENTI : max(fl, prev);
            } else {
                cnd = fl;
            }
            if (cnd < sS) atomicMin(&sS, cnd);
            if (sl != SENTI && sl < sS) atomicMin(&sS, sl);
        }
        // warp 0 resolves the negative while others head to the barrier
        if (base == 0 && warp == 0) {
            bool ok = (lane < NCANDS) && (candval != k);
            unsigned bal = __ballot_sync(0xffffffffu, ok) & 0xFFFFu;
            int neg = __shfl_sync(0xffffffffu, cand, bal ? (__ffs(bal) - 1) : 0);
            if (lane == 0) sNeg = neg;
        }
        __syncthreads();
        if (sS != SENTI || base + BTHR * 4 >= HW) break;   // exact fallback loops
        base += BTHR * 4;
        p = base + t * 4;
        v = make_int4(-1, -1, -1, -1);
        if (p + 3 < HW) v = *reinterpret_cast<const int4*>(mask + p);
        else {
            if (p     < HW) v.x = mask[p];
            if (p + 1 < HW) v.y = mask[p + 1];
            if (p + 2 < HW) v.z = mask[p + 2];
        }
    }

    bool valid = (sS != SENTI) && (k != 0);
    int fi = min(sF, HW - 1);
    int si = min(sS, HW - 1);
    int neg = sNeg;

    // ---- finalize: channel-parallel gathers ----
    float dap = 0.f, dan = 0.f;
    for (int c = t; c < BC; c += BTHR) {
        size_t off = (size_t)c * (size_t)HW;
        float a  = __ldg(sem + off + fi);
        float pv = __ldg(sem + off + si);
        float n  = __ldg(sem + off + neg);
        float e1 = a - pv + 1e-6f;
        float e2 = a - n  + 1e-6f;
        dap = fmaf(e1, e1, dap);
        dan = fmaf(e2, e2, dan);
    }
    sSq[t] = make_float2(dap, dan);
    __syncthreads();

    // warp 0: deterministic fixed-order reduction, then the packed atomic
    if (warp == 0) {
        float ta = 0.f, tn = 0.f;
        #pragma unroll
        for (int i = 0; i < BTHR / 32; i++) {
            float2 q = sSq[lane + i * 32];
            ta += q.x; tn += q.y;
        }
        #pragma unroll
        for (int o = 16; o; o >>= 1) {
            ta += __shfl_down_sync(0xffffffffu, ta, o);
            tn += __shfl_down_sync(0xffffffffu, tn, o);
        }
        if (lane == 0) {
            float per = fmaxf(sqrtf(ta) - sqrtf(tn) + 1.0f, 0.0f);
            unsigned long long fx = valid
                ? (unsigned long long)((double)per * 1073741824.0 + 0.5) : 0ULL;
            unsigned long long add = (fx << 13) |
                                     (valid ? (1ULL << 7) : 0ULL) | 1ULL;
            unsigned long long old = atomicAdd(&g_acc, add);
            if ((old & 0x7FULL) == (unsigned long long)(KIDS - 1)) {
                // last arriver: full packed total = old + our contribution
                unsigned long long full = old + add;
                unsigned cnt = (unsigned)((full >> 7) & 0x3FULL);
                double tot = (double)(full >> 13) * (1.0 / 1073741824.0);
                out[0] = (cnt > 0) ? (float)(tot / (double)cnt) : 0.0f;
                g_acc = 0ULL;        // reset for the next graph replay
            }
        }
    }
}

extern "C" void kernel_launch(void* const* d_in, const int* in_sizes, int n_in,
                              void* d_out, int out_size) {
    const float* sem  = (const float*)d_in[0];
    const int*   mask = (const int*)d_in[1];
    float*       out  = (float*)d_out;
    int HW = in_sizes[1];
    int BC = in_sizes[0] / HW;

    per_id_kernel<<<KIDS, BTHR>>>(sem, mask, out, HW, BC);
}